// round 3
// baseline (speedup 1.0000x reference)
#include <cuda_runtime.h>
#include <math.h>

#define NN 32768      // total nodes
#define FD 128        // input feature dim
#define HD 256        // hidden dim
#define NB 256        // graphs
#define MAXN 128      // nodes per graph
#define NE 524288     // edges
#define EPS_BN 1e-5f

// ---------------- scratch (device globals; no allocation allowed) ----------
__device__ float g_deg[NN];                         // degree -> dinv
__device__ float g_A[(size_t)NB * MAXN * MAXN];     // normalized adjacency (16 MB)
__device__ float g_buf0[(size_t)NN * HD];
__device__ float g_buf1[(size_t)NN * HD];
__device__ float g_buf2[(size_t)NN * HD];
__device__ float g_buf3[(size_t)NN * HD];
__device__ float g_sum[HD];
__device__ float g_sumsq[HD];
__device__ float g_small[NB * HD];

// ---------------- small utility kernels -----------------------------------
__global__ void k_initdeg() {
    int i = blockIdx.x * blockDim.x + threadIdx.x;
    if (i < NN) g_deg[i] = 1.0f;   // self loop contributes 1
}

__global__ void k_deg(const int* __restrict__ dst) {
    int e = blockIdx.x * blockDim.x + threadIdx.x;
    if (e < NE) {
        int g = e >> 11;  // E / B = 2048 edges per graph
        atomicAdd(&g_deg[g * MAXN + dst[e]], 1.0f);
    }
}

__global__ void k_dinv() {
    int i = blockIdx.x * blockDim.x + threadIdx.x;
    if (i < NN) g_deg[i] = rsqrtf(fmaxf(g_deg[i], 1.0f));
}

__global__ void k_clearA() {
    size_t i = (size_t)blockIdx.x * blockDim.x + threadIdx.x;
    if (i < (size_t)NB * MAXN * MAXN) g_A[i] = 0.0f;
}

__global__ void k_buildA(const int* __restrict__ src, const int* __restrict__ dst) {
    int e = blockIdx.x * blockDim.x + threadIdx.x;
    if (e < NE) {
        int g = e >> 11;
        int s = src[e], d = dst[e];
        float nrm = g_deg[g * MAXN + s] * g_deg[g * MAXN + d];
        atomicAdd(&g_A[((size_t)g * MAXN + d) * MAXN + s], nrm);
    }
}

__global__ void k_diagA() {
    int i = blockIdx.x * blockDim.x + threadIdx.x;
    if (i < NN) {
        int g = i / MAXN, l = i % MAXN;
        float di = g_deg[i];
        g_A[((size_t)g * MAXN + l) * MAXN + l] += di * di;
    }
}

__global__ void k_clearsums() {
    int i = threadIdx.x;
    if (i < HD) { g_sum[i] = 0.0f; g_sumsq[i] = 0.0f; }
}

// ---------------- generic tiled fp32 GEMM (double-buffered) ---------------
// C[M,N] = A[M,K] @ B[K,N] (+bias) (+relu). Batched via blockIdx.z strides.
// M,N multiples of 64; K multiple of 16.
__global__ void __launch_bounds__(256) k_gemm(
    const float* __restrict__ A, const float* __restrict__ B,
    const float* __restrict__ bias, float* __restrict__ C,
    int M, int N, int K, int relu,
    long sA, long sB, long sC)
{
    __shared__ float As[2][16][64];
    __shared__ float Bs[2][16][64];
    long g = blockIdx.z;
    A += g * sA; B += g * sB; C += g * sC;

    const int tid = threadIdx.x;
    const int ty = tid >> 4, tx = tid & 15;
    const int row0 = blockIdx.y * 64, col0 = blockIdx.x * 64;
    const int am = tid >> 2, ak = (tid & 3) * 4;   // A tile load map
    const int bk = tid >> 4, bn = (tid & 15) * 4;  // B tile load map

    const float* Ap = A + (size_t)(row0 + am) * K + ak;
    const float* Bp = B + (size_t)bk * N + col0 + bn;
    float acc[4][4] = {};

    // prologue: load tile 0
    float4 a4 = *(const float4*)Ap;
    float4 b4 = *(const float4*)Bp;
    As[0][ak + 0][am] = a4.x; As[0][ak + 1][am] = a4.y;
    As[0][ak + 2][am] = a4.z; As[0][ak + 3][am] = a4.w;
    *(float4*)&Bs[0][bk][bn] = b4;
    __syncthreads();

    int nk = K / 16;
    for (int it = 0; it < nk; it++) {
        int cur = it & 1, nxt = cur ^ 1;
        if (it + 1 < nk) {
            Ap += 16;
            Bp += (size_t)16 * N;
            a4 = *(const float4*)Ap;
            b4 = *(const float4*)Bp;
        }
#pragma unroll
        for (int k = 0; k < 16; k++) {
            float4 av = *(const float4*)&As[cur][k][ty * 4];
            float4 bv = *(const float4*)&Bs[cur][k][tx * 4];
            float a[4] = {av.x, av.y, av.z, av.w};
            float b[4] = {bv.x, bv.y, bv.z, bv.w};
#pragma unroll
            for (int i = 0; i < 4; i++)
#pragma unroll
                for (int j = 0; j < 4; j++)
                    acc[i][j] += a[i] * b[j];
        }
        if (it + 1 < nk) {
            __syncthreads();
            As[nxt][ak + 0][am] = a4.x; As[nxt][ak + 1][am] = a4.y;
            As[nxt][ak + 2][am] = a4.z; As[nxt][ak + 3][am] = a4.w;
            *(float4*)&Bs[nxt][bk][bn] = b4;
            __syncthreads();
        }
    }

#pragma unroll
    for (int i = 0; i < 4; i++) {
        int r = row0 + ty * 4 + i;
#pragma unroll
        for (int j = 0; j < 4; j++) {
            int c = col0 + tx * 4 + j;
            float v = acc[i][j];
            if (bias) v += bias[c];
            if (relu) v = fmaxf(v, 0.0f);
            C[(size_t)r * N + c] = v;
        }
    }
}

// ---------------- bilinear edge decoder: adj[g] = sig(ZW[g] @ z[g]^T) -----
// per graph: (128 x 256) @ (256 x 128), diag zeroed
__global__ void __launch_bounds__(256) k_edge(
    const float* __restrict__ ZW, const float* __restrict__ z,
    float* __restrict__ adj)
{
    __shared__ float As[16][64];
    __shared__ float Bs[16][64];
    int g = blockIdx.z;
    const float* Ab = ZW + (size_t)g * MAXN * HD;
    const float* Bb = z  + (size_t)g * MAXN * HD;
    const int tid = threadIdx.x;
    const int ty = tid >> 4, tx = tid & 15;
    const int row0 = blockIdx.y * 64, col0 = blockIdx.x * 64;
    const int am = tid >> 2, ak = (tid & 3) * 4;

    const float* Ap = Ab + (size_t)(row0 + am) * HD + ak;
    const float* Bp = Bb + (size_t)(col0 + am) * HD + ak;
    float acc[4][4] = {};

    for (int k0 = 0; k0 < HD; k0 += 16) {
        float4 a4 = *(const float4*)Ap; Ap += 16;
        float4 b4 = *(const float4*)Bp; Bp += 16;
        As[ak + 0][am] = a4.x; As[ak + 1][am] = a4.y;
        As[ak + 2][am] = a4.z; As[ak + 3][am] = a4.w;
        Bs[ak + 0][am] = b4.x; Bs[ak + 1][am] = b4.y;
        Bs[ak + 2][am] = b4.z; Bs[ak + 3][am] = b4.w;
        __syncthreads();
#pragma unroll
        for (int k = 0; k < 16; k++) {
            float4 av = *(const float4*)&As[k][ty * 4];
            float4 bv = *(const float4*)&Bs[k][tx * 4];
            float a[4] = {av.x, av.y, av.z, av.w};
            float b[4] = {bv.x, bv.y, bv.z, bv.w};
#pragma unroll
            for (int i = 0; i < 4; i++)
#pragma unroll
                for (int j = 0; j < 4; j++)
                    acc[i][j] += a[i] * b[j];
        }
        __syncthreads();
    }

#pragma unroll
    for (int i = 0; i < 4; i++) {
        int n = row0 + ty * 4 + i;
#pragma unroll
        for (int j = 0; j < 4; j++) {
            int m = col0 + tx * 4 + j;
            float v = 1.0f / (1.0f + expf(-acc[i][j]));
            if (n == m) v = 0.0f;
            adj[(size_t)g * MAXN * MAXN + (size_t)n * MAXN + m] = v;
        }
    }
}

// ---------------- BN stats: per-column sum & sumsq over NN rows -----------
__global__ void k_bnstats(const float* __restrict__ x) {
    int c = threadIdx.x;          // 0..255
    int r0 = blockIdx.x * 128;
    float s = 0.0f, ss = 0.0f;
    for (int r = 0; r < 128; r++) {
        float v = x[(size_t)(r0 + r) * HD + c];
        s += v; ss += v * v;
    }
    atomicAdd(&g_sum[c], s);
    atomicAdd(&g_sumsq[c], ss);
}

// mode 0: y = bn(x)          (feature decoder)
// mode 1: y = relu(relu(bn(x)) + res)   (GCN block)
__global__ void k_bnapply(const float* __restrict__ x, const float* __restrict__ res,
                          const float* __restrict__ gam, const float* __restrict__ bet,
                          float* __restrict__ y, int mode)
{
    size_t i = (size_t)blockIdx.x * blockDim.x + threadIdx.x;
    if (i >= (size_t)NN * HD) return;
    int c = (int)(i & (HD - 1));
    float m = g_sum[c] * (1.0f / NN);
    float v = g_sumsq[c] * (1.0f / NN) - m * m;
    float w = (x[i] - m) * rsqrtf(v + EPS_BN) * gam[c] + bet[c];
    if (mode) {
        w = fmaxf(w, 0.0f) + res[i];
        w = fmaxf(w, 0.0f);
    }
    y[i] = w;
}

// ---------------- row-wise L2 normalize (warp per row) --------------------
__global__ void k_l2(const float* __restrict__ z, float* __restrict__ out) {
    int row = blockIdx.x * 8 + (threadIdx.x >> 5);
    int lane = threadIdx.x & 31;
    const float* p = z + (size_t)row * HD;
    float s = 0.0f;
    for (int k = lane; k < HD; k += 32) { float v = p[k]; s += v * v; }
#pragma unroll
    for (int o = 16; o; o >>= 1) s += __shfl_xor_sync(0xFFFFFFFFu, s, o);
    float inv = 1.0f / fmaxf(sqrtf(s), 1e-12f);
    for (int k = lane; k < HD; k += 32) out[(size_t)row * HD + k] = p[k] * inv;
}

// ---------------- per-graph max pool --------------------------------------
__global__ void k_pool(const float* __restrict__ z, float* __restrict__ zg) {
    int g = blockIdx.x;
    int c = threadIdx.x;
    float m = z[((size_t)g * MAXN) * HD + c];
    for (int r = 1; r < MAXN; r++)
        m = fmaxf(m, z[((size_t)g * MAXN + r) * HD + c]);
    zg[(size_t)g * HD + c] = m;
}

// ---------------- host orchestration --------------------------------------
extern "C" void kernel_launch(void* const* d_in, const int* in_sizes, int n_in,
                              void* d_out, int out_size)
{
    const float* x   = (const float*)d_in[0];
    const int*   src = (const int*)d_in[1];
    const int*   dst = (const int*)d_in[2];

    // Index map: setup_inputs dict order vs reference signature order
    // in_sizes[7]: 65536 (=gcn_w1, dict order) or 32768 (=sc_w0, sig order)
    int i_gw[3], i_gb[3], i_bg[3], i_bb[3], i_scw, i_scb;
    if (in_sizes[7] == 65536) {  // dict order
        for (int l = 0; l < 3; l++) {
            i_gw[l] = 3 + 4 * l; i_gb[l] = 4 + 4 * l;
            i_bg[l] = 5 + 4 * l; i_bb[l] = 6 + 4 * l;
        }
        i_scw = 15; i_scb = 16;
    } else {                      // signature order
        i_gw[0] = 3; i_gb[0] = 4; i_bg[0] = 5; i_bb[0] = 6;
        i_scw = 7; i_scb = 8;
        i_gw[1] = 9;  i_gb[1] = 10; i_bg[1] = 11; i_bb[1] = 12;
        i_gw[2] = 13; i_gb[2] = 14; i_bg[2] = 15; i_bb[2] = 16;
    }
    const float* gw[3]; const float* gb[3]; const float* bg[3]; const float* bb[3];
    for (int l = 0; l < 3; l++) {
        gw[l] = (const float*)d_in[i_gw[l]];
        gb[l] = (const float*)d_in[i_gb[l]];
        bg[l] = (const float*)d_in[i_bg[l]];
        bb[l] = (const float*)d_in[i_bb[l]];
    }
    const float* scw  = (const float*)d_in[i_scw];
    const float* scb  = (const float*)d_in[i_scb];
    const float* ew   = (const float*)d_in[17];
    const float* fw0  = (const float*)d_in[18];
    const float* fb0  = (const float*)d_in[19];
    const float* fg0  = (const float*)d_in[20];
    const float* fbe0 = (const float*)d_in[21];
    const float* fw1  = (const float*)d_in[22];
    const float* fb1  = (const float*)d_in[23];
    const float* fg1  = (const float*)d_in[24];
    const float* fbe1 = (const float*)d_in[25];
    const float* fw2  = (const float*)d_in[26];
    const float* fb2  = (const float*)d_in[27];
    const float* pw0  = (const float*)d_in[28];
    const float* pb0  = (const float*)d_in[29];
    const float* pw1  = (const float*)d_in[30];
    const float* pb1  = (const float*)d_in[31];

    float *pA, *pb0_, *pb1_, *pb2_, *pb3_, *psm;
    cudaGetSymbolAddress((void**)&pA,   g_A);
    cudaGetSymbolAddress((void**)&pb0_, g_buf0);
    cudaGetSymbolAddress((void**)&pb1_, g_buf1);
    cudaGetSymbolAddress((void**)&pb2_, g_buf2);
    cudaGetSymbolAddress((void**)&pb3_, g_buf3);
    cudaGetSymbolAddress((void**)&psm,  g_small);

    float* out_z     = (float*)d_out;                      // 32768*256
    float* out_adj   = out_z + (size_t)NN * HD;            // 256*128*128
    float* out_xrec  = out_adj + (size_t)NB * MAXN * MAXN; // 32768*128
    float* out_zg    = out_xrec + (size_t)NN * FD;         // 256*256
    float* out_zgmlp = out_zg + (size_t)NB * HD;           // 256*256

    // ---- build normalized adjacency (reused by all 3 layers) ----
    k_initdeg<<<NN / 256, 256>>>();
    k_deg<<<NE / 256, 256>>>(dst);
    k_dinv<<<NN / 256, 256>>>();
    k_clearA<<<(NB * MAXN * MAXN) / 256, 256>>>();
    k_buildA<<<NE / 256, 256>>>(src, dst);
    k_diagA<<<NN / 256, 256>>>();

    dim3 gBig(HD / 64, NN / 64);     // 4 x 512, full-size GEMMs (N=256)
    dim3 gAgg(HD / 64, MAXN / 64, NB);  // batched aggregation
    dim3 gEdge(MAXN / 64, MAXN / 64, NB);
    dim3 gXrec(FD / 64, NN / 64);
    dim3 gSmall(HD / 64, NB / 64);
    int nElem = (NN * HD) / 256;

    // ---- GCN layer 0 ----
    k_gemm<<<gBig, 256>>>(x, gw[0], nullptr, pb1_, NN, HD, FD, 0, 0, 0, 0);
    k_gemm<<<gBig, 256>>>(x, scw, scb, pb3_, NN, HD, FD, 0, 0, 0, 0);   // shortcut
    k_gemm<<<gAgg, 256>>>(pA, pb1_, gb[0], pb2_, MAXN, HD, MAXN, 0,
                          (long)MAXN * MAXN, (long)MAXN * HD, (long)MAXN * HD);
    k_clearsums<<<1, 256>>>();
    k_bnstats<<<NN / 128, 256>>>(pb2_);
    k_bnapply<<<nElem, 256>>>(pb2_, pb3_, bg[0], bb[0], pb0_, 1);

    // ---- GCN layer 1 (residual = input) ----
    k_gemm<<<gBig, 256>>>(pb0_, gw[1], nullptr, pb1_, NN, HD, HD, 0, 0, 0, 0);
    k_gemm<<<gAgg, 256>>>(pA, pb1_, gb[1], pb2_, MAXN, HD, MAXN, 0,
                          (long)MAXN * MAXN, (long)MAXN * HD, (long)MAXN * HD);
    k_clearsums<<<1, 256>>>();
    k_bnstats<<<NN / 128, 256>>>(pb2_);
    k_bnapply<<<nElem, 256>>>(pb2_, pb0_, bg[1], bb[1], pb3_, 1);

    // ---- GCN layer 2 ----
    k_gemm<<<gBig, 256>>>(pb3_, gw[2], nullptr, pb1_, NN, HD, HD, 0, 0, 0, 0);
    k_gemm<<<gAgg, 256>>>(pA, pb1_, gb[2], pb2_, MAXN, HD, MAXN, 0,
                          (long)MAXN * MAXN, (long)MAXN * HD, (long)MAXN * HD);
    k_clearsums<<<1, 256>>>();
    k_bnstats<<<NN / 128, 256>>>(pb2_);
    k_bnapply<<<nElem, 256>>>(pb2_, pb3_, bg[2], bb[2], pb0_, 1);

    // ---- L2 normalize -> z (written straight to output) ----
    k_l2<<<NN / 8, 256>>>(pb0_, out_z);

    // ---- bilinear edge decoder ----
    k_gemm<<<gBig, 256>>>(out_z, ew, nullptr, pb1_, NN, HD, HD, 0, 0, 0, 0);
    k_edge<<<gEdge, 256>>>(pb1_, out_z, out_adj);

    // ---- feature decoder ----
    k_gemm<<<gBig, 256>>>(out_z, fw0, fb0, pb2_, NN, HD, HD, 1, 0, 0, 0);
    k_clearsums<<<1, 256>>>();
    k_bnstats<<<NN / 128, 256>>>(pb2_);
    k_bnapply<<<nElem, 256>>>(pb2_, pb2_, fg0, fbe0, pb3_, 0);
    k_gemm<<<gBig, 256>>>(pb3_, fw1, fb1, pb1_, NN, HD, HD, 1, 0, 0, 0);
    k_clearsums<<<1, 256>>>();
    k_bnstats<<<NN / 128, 256>>>(pb1_);
    k_bnapply<<<nElem, 256>>>(pb1_, pb1_, fg1, fbe1, pb2_, 0);
    k_gemm<<<gXrec, 256>>>(pb2_, fw2, fb2, out_xrec, NN, FD, HD, 0, 0, 0, 0);

    // ---- pooling + MLP head ----
    k_pool<<<NB, HD>>>(out_z, out_zg);
    k_gemm<<<gSmall, 256>>>(out_zg, pw0, pb0, psm, NB, HD, HD, 1, 0, 0, 0);
    k_gemm<<<gSmall, 256>>>(psm, pw1, pb1, out_zgmlp, NB, HD, HD, 0, 0, 0, 0);
}

// round 5
// speedup vs baseline: 1.3097x; 1.3097x over previous
#include <cuda_runtime.h>
#include <math.h>

#define NN 32768      // total nodes
#define FD 128        // input feature dim
#define HD 256        // hidden dim
#define NB 256        // graphs
#define MAXN 128      // nodes per graph
#define NE 524288     // edges
#define EPS_BN 1e-5f

// ---------------- scratch (device globals; no allocation allowed) ----------
__device__ float g_deg[NN];
__device__ float g_A[(size_t)NB * MAXN * MAXN];     // normalized adjacency (16 MB)
__device__ float g_buf0[(size_t)NN * HD];
__device__ float g_buf1[(size_t)NN * HD];
__device__ float g_buf2[(size_t)NN * HD];
__device__ float g_buf3[(size_t)NN * HD];
__device__ float g_sum[HD];
__device__ float g_sumsq[HD];
__device__ float g_small[NB * HD];

// ---------------- small utility kernels -----------------------------------
__global__ void k_initdeg() {
    int i = blockIdx.x * blockDim.x + threadIdx.x;
    if (i < NN) g_deg[i] = 1.0f;
}

__global__ void k_deg(const int* __restrict__ dst) {
    int e = blockIdx.x * blockDim.x + threadIdx.x;
    if (e < NE) {
        int g = e >> 11;  // E / B = 2048 edges per graph
        atomicAdd(&g_deg[g * MAXN + dst[e]], 1.0f);
    }
}

__global__ void k_dinv() {
    int i = blockIdx.x * blockDim.x + threadIdx.x;
    if (i < NN) g_deg[i] = rsqrtf(fmaxf(g_deg[i], 1.0f));
}

__global__ void k_clearA() {
    size_t i = (size_t)blockIdx.x * blockDim.x + threadIdx.x;
    if (i < (size_t)NB * MAXN * MAXN) g_A[i] = 0.0f;
}

__global__ void k_buildA(const int* __restrict__ src, const int* __restrict__ dst) {
    int e = blockIdx.x * blockDim.x + threadIdx.x;
    if (e < NE) {
        int g = e >> 11;
        int s = src[e], d = dst[e];
        float nrm = g_deg[g * MAXN + s] * g_deg[g * MAXN + d];
        atomicAdd(&g_A[((size_t)g * MAXN + d) * MAXN + s], nrm);
    }
}

__global__ void k_diagA() {
    int i = blockIdx.x * blockDim.x + threadIdx.x;
    if (i < NN) {
        int g = i / MAXN, l = i % MAXN;
        float di = g_deg[i];
        g_A[((size_t)g * MAXN + l) * MAXN + l] += di * di;
    }
}

__global__ void k_clearsums() {
    int i = threadIdx.x;
    if (i < HD) { g_sum[i] = 0.0f; g_sumsq[i] = 0.0f; }
}

// ---------------- 3xTF32 tensor-core GEMM ----------------------------------
// C[.,N] = A[.,K] @ B[K,N] (+bias)(+relu), batched via blockIdx.z strides.
// Block tile 128x128x32, 8 warps (2x4), warp tile 64x32, mma.m16n8k8.tf32.
// Split precision: a = hi + lo; acc += ah*bh + ah*bl + al*bh  (~fp32 accuracy)

__device__ __forceinline__ unsigned f2tf(float f) {
    unsigned u;
    asm("cvt.rna.tf32.f32 %0, %1;" : "=r"(u) : "f"(f));
    return u;
}

__device__ __forceinline__ void split_tf(float f, unsigned& h, unsigned& l) {
    h = f2tf(f);
    l = f2tf(f - __uint_as_float(h));
}

#define MMA_TF32(d, a0, a1, a2, a3, b0, b1) \
    asm volatile("mma.sync.aligned.m16n8k8.row.col.f32.tf32.tf32.f32 " \
                 "{%0,%1,%2,%3},{%4,%5,%6,%7},{%8,%9},{%0,%1,%2,%3};" \
                 : "+f"(d[0]), "+f"(d[1]), "+f"(d[2]), "+f"(d[3]) \
                 : "r"(a0), "r"(a1), "r"(a2), "r"(a3), "r"(b0), "r"(b1))

#define AS_STRIDE 36
#define BS_STRIDE 132
#define SM_AH 0
#define SM_AL (128 * AS_STRIDE)
#define SM_BH (2 * 128 * AS_STRIDE)
#define SM_BL (2 * 128 * AS_STRIDE + 32 * BS_STRIDE)
#define SMEM3_BYTES ((2 * 128 * AS_STRIDE + 2 * 32 * BS_STRIDE) * 4)

__global__ void __launch_bounds__(256) k_tgemm3(
    const float* __restrict__ A, const float* __restrict__ B,
    const float* __restrict__ bias, float* __restrict__ C,
    int N, int K, int relu, long sA, long sB, long sC)
{
    extern __shared__ unsigned dsm[];
    unsigned* Ah = dsm + SM_AH;
    unsigned* Al = dsm + SM_AL;
    unsigned* Bh = dsm + SM_BH;
    unsigned* Bl = dsm + SM_BL;

    long g = blockIdx.z;
    A += g * sA; B += g * sB; C += g * sC;

    const int tid = threadIdx.x, lane = tid & 31, wid = tid >> 5;
    const int wm = wid >> 2, wn = wid & 3;      // warp tile (wm*64, wn*32)
    const int gp = lane >> 2, tg = lane & 3;
    const int row0 = blockIdx.y * 128, col0 = blockIdx.x * 128;

    const int la_r = tid >> 3, la_c = (tid & 7) * 4;   // A loads: 4 x (row+32j)
    const int lb_r = tid >> 5, lb_c = (tid & 31) * 4;  // B loads: 4 x (row+8j)

    const float* Ap = A + (size_t)(row0 + la_r) * K + la_c;
    const float* Bp = B + (size_t)lb_r * N + col0 + lb_c;

    float4 pa[4], pb[4];
#pragma unroll
    for (int j = 0; j < 4; j++) {
        pa[j] = *(const float4*)(Ap + (size_t)(j * 32) * K);
        pb[j] = *(const float4*)(Bp + (size_t)(j * 8) * N);
    }

    float acc[4][4][4] = {};
    const int nk = K >> 5;

    for (int kt = 0; kt < nk; kt++) {
        if (kt) __syncthreads();
#pragma unroll
        for (int j = 0; j < 4; j++) {
            uint4 vh, vl;
            split_tf(pa[j].x, vh.x, vl.x); split_tf(pa[j].y, vh.y, vl.y);
            split_tf(pa[j].z, vh.z, vl.z); split_tf(pa[j].w, vh.w, vl.w);
            *(uint4*)&Ah[(la_r + j * 32) * AS_STRIDE + la_c] = vh;
            *(uint4*)&Al[(la_r + j * 32) * AS_STRIDE + la_c] = vl;
            split_tf(pb[j].x, vh.x, vl.x); split_tf(pb[j].y, vh.y, vl.y);
            split_tf(pb[j].z, vh.z, vl.z); split_tf(pb[j].w, vh.w, vl.w);
            *(uint4*)&Bh[(lb_r + j * 8) * BS_STRIDE + lb_c] = vh;
            *(uint4*)&Bl[(lb_r + j * 8) * BS_STRIDE + lb_c] = vl;
        }
        __syncthreads();
        if (kt + 1 < nk) {
            Ap += 32;
            Bp += (size_t)32 * N;
#pragma unroll
            for (int j = 0; j < 4; j++) {
                pa[j] = *(const float4*)(Ap + (size_t)(j * 32) * K);
                pb[j] = *(const float4*)(Bp + (size_t)(j * 8) * N);
            }
        }
#pragma unroll
        for (int s = 0; s < 4; s++) {
            const int ks = s * 8;
            unsigned ah[4][4], al[4][4], bh[4][2], bl[4][2];
#pragma unroll
            for (int mi = 0; mi < 4; mi++) {
                int r = wm * 64 + mi * 16 + gp;
                ah[mi][0] = Ah[r * AS_STRIDE + ks + tg];
                ah[mi][1] = Ah[(r + 8) * AS_STRIDE + ks + tg];
                ah[mi][2] = Ah[r * AS_STRIDE + ks + tg + 4];
                ah[mi][3] = Ah[(r + 8) * AS_STRIDE + ks + tg + 4];
                al[mi][0] = Al[r * AS_STRIDE + ks + tg];
                al[mi][1] = Al[(r + 8) * AS_STRIDE + ks + tg];
                al[mi][2] = Al[r * AS_STRIDE + ks + tg + 4];
                al[mi][3] = Al[(r + 8) * AS_STRIDE + ks + tg + 4];
            }
#pragma unroll
            for (int ni = 0; ni < 4; ni++) {
                int c = wn * 32 + ni * 8 + gp;
                bh[ni][0] = Bh[(ks + tg) * BS_STRIDE + c];
                bh[ni][1] = Bh[(ks + tg + 4) * BS_STRIDE + c];
                bl[ni][0] = Bl[(ks + tg) * BS_STRIDE + c];
                bl[ni][1] = Bl[(ks + tg + 4) * BS_STRIDE + c];
            }
#pragma unroll
            for (int mi = 0; mi < 4; mi++)
#pragma unroll
                for (int ni = 0; ni < 4; ni++) {
                    MMA_TF32(acc[mi][ni], ah[mi][0], ah[mi][1], ah[mi][2], ah[mi][3],
                             bl[ni][0], bl[ni][1]);
                    MMA_TF32(acc[mi][ni], al[mi][0], al[mi][1], al[mi][2], al[mi][3],
                             bh[ni][0], bh[ni][1]);
                    MMA_TF32(acc[mi][ni], ah[mi][0], ah[mi][1], ah[mi][2], ah[mi][3],
                             bh[ni][0], bh[ni][1]);
                }
        }
    }

#pragma unroll
    for (int mi = 0; mi < 4; mi++) {
        int r = row0 + wm * 64 + mi * 16 + gp;
#pragma unroll
        for (int ni = 0; ni < 4; ni++) {
            int c = col0 + wn * 32 + ni * 8 + tg * 2;
            float v0 = acc[mi][ni][0], v1 = acc[mi][ni][1];
            float v2 = acc[mi][ni][2], v3 = acc[mi][ni][3];
            if (bias) {
                float b0 = bias[c], b1 = bias[c + 1];
                v0 += b0; v1 += b1; v2 += b0; v3 += b1;
            }
            if (relu) {
                v0 = fmaxf(v0, 0.0f); v1 = fmaxf(v1, 0.0f);
                v2 = fmaxf(v2, 0.0f); v3 = fmaxf(v3, 0.0f);
            }
            float2 w0 = {v0, v1}, w1 = {v2, v3};
            *(float2*)&C[(size_t)r * N + c] = w0;
            *(float2*)&C[(size_t)(r + 8) * N + c] = w1;
        }
    }
}

// ---------------- edge decoder: adj[g] = sigmoid(ZW[g] @ z[g]^T), diag=0 ---
// per graph: (128 x 256) @ (256 x 128).  One block per graph. 3xTF32.
__global__ void __launch_bounds__(256) k_tedge3(
    const float* __restrict__ ZW, const float* __restrict__ z,
    float* __restrict__ adj)
{
    extern __shared__ unsigned dsm[];
    unsigned* Ah = dsm + SM_AH;
    unsigned* Al = dsm + SM_AL;
    unsigned* Bh = dsm + SM_BH;
    unsigned* Bl = dsm + SM_BL;

    const int g = blockIdx.z;
    const float* Ab = ZW + (size_t)g * MAXN * HD;
    const float* Bb = z  + (size_t)g * MAXN * HD;

    const int tid = threadIdx.x, lane = tid & 31, wid = tid >> 5;
    const int wm = wid >> 2, wn = wid & 3;
    const int gp = lane >> 2, tg = lane & 3;

    const int la_r = tid >> 3, la_c = (tid & 7) * 4;   // A: row-major
    const int lb_n = tid >> 3, lb_c = (tid & 7) * 4;   // B: z rows, k along float4

    float acc[4][4][4] = {};

    for (int kt = 0; kt < HD / 32; kt++) {
        const int k0 = kt * 32;
        if (kt) __syncthreads();
#pragma unroll
        for (int j = 0; j < 4; j++) {
            float4 a = *(const float4*)(Ab + (size_t)(la_r + j * 32) * HD + k0 + la_c);
            uint4 vh, vl;
            split_tf(a.x, vh.x, vl.x); split_tf(a.y, vh.y, vl.y);
            split_tf(a.z, vh.z, vl.z); split_tf(a.w, vh.w, vl.w);
            *(uint4*)&Ah[(la_r + j * 32) * AS_STRIDE + la_c] = vh;
            *(uint4*)&Al[(la_r + j * 32) * AS_STRIDE + la_c] = vl;
            int n = lb_n + j * 32;
            float4 b = *(const float4*)(Bb + (size_t)n * HD + k0 + lb_c);
            unsigned h, l;
            split_tf(b.x, h, l); Bh[(lb_c + 0) * BS_STRIDE + n] = h; Bl[(lb_c + 0) * BS_STRIDE + n] = l;
            split_tf(b.y, h, l); Bh[(lb_c + 1) * BS_STRIDE + n] = h; Bl[(lb_c + 1) * BS_STRIDE + n] = l;
            split_tf(b.z, h, l); Bh[(lb_c + 2) * BS_STRIDE + n] = h; Bl[(lb_c + 2) * BS_STRIDE + n] = l;
            split_tf(b.w, h, l); Bh[(lb_c + 3) * BS_STRIDE + n] = h; Bl[(lb_c + 3) * BS_STRIDE + n] = l;
        }
        __syncthreads();
#pragma unroll
        for (int s = 0; s < 4; s++) {
            const int ks = s * 8;
            unsigned ah[4][4], al[4][4], bh[4][2], bl[4][2];
#pragma unroll
            for (int mi = 0; mi < 4; mi++) {
                int r = wm * 64 + mi * 16 + gp;
                ah[mi][0] = Ah[r * AS_STRIDE + ks + tg];
                ah[mi][1] = Ah[(r + 8) * AS_STRIDE + ks + tg];
                ah[mi][2] = Ah[r * AS_STRIDE + ks + tg + 4];
                ah[mi][3] = Ah[(r + 8) * AS_STRIDE + ks + tg + 4];
                al[mi][0] = Al[r * AS_STRIDE + ks + tg];
                al[mi][1] = Al[(r + 8) * AS_STRIDE + ks + tg];
                al[mi][2] = Al[r * AS_STRIDE + ks + tg + 4];
                al[mi][3] = Al[(r + 8) * AS_STRIDE + ks + tg + 4];
            }
#pragma unroll
            for (int ni = 0; ni < 4; ni++) {
                int c = wn * 32 + ni * 8 + gp;
                bh[ni][0] = Bh[(ks + tg) * BS_STRIDE + c];
                bh[ni][1] = Bh[(ks + tg + 4) * BS_STRIDE + c];
                bl[ni][0] = Bl[(ks + tg) * BS_STRIDE + c];
                bl[ni][1] = Bl[(ks + tg + 4) * BS_STRIDE + c];
            }
#pragma unroll
            for (int mi = 0; mi < 4; mi++)
#pragma unroll
                for (int ni = 0; ni < 4; ni++) {
                    MMA_TF32(acc[mi][ni], ah[mi][0], ah[mi][1], ah[mi][2], ah[mi][3],
                             bl[ni][0], bl[ni][1]);
                    MMA_TF32(acc[mi][ni], al[mi][0], al[mi][1], al[mi][2], al[mi][3],
                             bh[ni][0], bh[ni][1]);
                    MMA_TF32(acc[mi][ni], ah[mi][0], ah[mi][1], ah[mi][2], ah[mi][3],
                             bh[ni][0], bh[ni][1]);
                }
        }
    }

    float* out = adj + (size_t)g * MAXN * MAXN;
#pragma unroll
    for (int mi = 0; mi < 4; mi++) {
        int n = wm * 64 + mi * 16 + gp;
#pragma unroll
        for (int ni = 0; ni < 4; ni++) {
            int m = wn * 32 + ni * 8 + tg * 2;
            float v0 = 1.0f / (1.0f + expf(-acc[mi][ni][0]));
            float v1 = 1.0f / (1.0f + expf(-acc[mi][ni][1]));
            float v2 = 1.0f / (1.0f + expf(-acc[mi][ni][2]));
            float v3 = 1.0f / (1.0f + expf(-acc[mi][ni][3]));
            if (n == m) v0 = 0.0f;
            if (n == m + 1) v1 = 0.0f;
            if (n + 8 == m) v2 = 0.0f;
            if (n + 8 == m + 1) v3 = 0.0f;
            float2 w0 = {v0, v1}, w1 = {v2, v3};
            *(float2*)&out[(size_t)n * MAXN + m] = w0;
            *(float2*)&out[(size_t)(n + 8) * MAXN + m] = w1;
        }
    }
}

// ---------------- BN stats: per-column sum & sumsq over NN rows ------------
__global__ void k_bnstats(const float* __restrict__ x) {
    int c = threadIdx.x;
    int r0 = blockIdx.x * 128;
    float s = 0.0f, ss = 0.0f;
    for (int r = 0; r < 128; r++) {
        float v = x[(size_t)(r0 + r) * HD + c];
        s += v; ss += v * v;
    }
    atomicAdd(&g_sum[c], s);
    atomicAdd(&g_sumsq[c], ss);
}

// mode 0: y = bn(x)        mode 1: y = relu(relu(bn(x)) + res)
__global__ void k_bnapply(const float* __restrict__ x, const float* __restrict__ res,
                          const float* __restrict__ gam, const float* __restrict__ bet,
                          float* __restrict__ y, int mode)
{
    size_t i = (size_t)blockIdx.x * blockDim.x + threadIdx.x;
    if (i >= (size_t)NN * HD) return;
    int c = (int)(i & (HD - 1));
    float m = g_sum[c] * (1.0f / NN);
    float v = g_sumsq[c] * (1.0f / NN) - m * m;
    float w = (x[i] - m) * rsqrtf(v + EPS_BN) * gam[c] + bet[c];
    if (mode) {
        w = fmaxf(w, 0.0f) + res[i];
        w = fmaxf(w, 0.0f);
    }
    y[i] = w;
}

// ---------------- row-wise L2 normalize (warp per row) ---------------------
__global__ void k_l2(const float* __restrict__ z, float* __restrict__ out) {
    int row = blockIdx.x * 8 + (threadIdx.x >> 5);
    int lane = threadIdx.x & 31;
    const float* p = z + (size_t)row * HD;
    float s = 0.0f;
    for (int k = lane; k < HD; k += 32) { float v = p[k]; s += v * v; }
#pragma unroll
    for (int o = 16; o; o >>= 1) s += __shfl_xor_sync(0xFFFFFFFFu, s, o);
    float inv = 1.0f / fmaxf(sqrtf(s), 1e-12f);
    for (int k = lane; k < HD; k += 32) out[(size_t)row * HD + k] = p[k] * inv;
}

// ---------------- per-graph max pool ---------------------------------------
__global__ void k_pool(const float* __restrict__ z, float* __restrict__ zg) {
    int g = blockIdx.x;
    int c = threadIdx.x;
    float m = z[((size_t)g * MAXN) * HD + c];
    for (int r = 1; r < MAXN; r++)
        m = fmaxf(m, z[((size_t)g * MAXN + r) * HD + c]);
    zg[(size_t)g * HD + c] = m;
}

// ---------------- host orchestration ---------------------------------------
extern "C" void kernel_launch(void* const* d_in, const int* in_sizes, int n_in,
                              void* d_out, int out_size)
{
    const float* x   = (const float*)d_in[0];
    const int*   src = (const int*)d_in[1];
    const int*   dst = (const int*)d_in[2];

    int i_gw[3], i_gb[3], i_bg[3], i_bb[3], i_scw, i_scb;
    if (in_sizes[7] == 65536) {  // dict order
        for (int l = 0; l < 3; l++) {
            i_gw[l] = 3 + 4 * l; i_gb[l] = 4 + 4 * l;
            i_bg[l] = 5 + 4 * l; i_bb[l] = 6 + 4 * l;
        }
        i_scw = 15; i_scb = 16;
    } else {                      // signature order
        i_gw[0] = 3; i_gb[0] = 4; i_bg[0] = 5; i_bb[0] = 6;
        i_scw = 7; i_scb = 8;
        i_gw[1] = 9;  i_gb[1] = 10; i_bg[1] = 11; i_bb[1] = 12;
        i_gw[2] = 13; i_gb[2] = 14; i_bg[2] = 15; i_bb[2] = 16;
    }
    const float* gw[3]; const float* gb[3]; const float* bg[3]; const float* bb[3];
    for (int l = 0; l < 3; l++) {
        gw[l] = (const float*)d_in[i_gw[l]];
        gb[l] = (const float*)d_in[i_gb[l]];
        bg[l] = (const float*)d_in[i_bg[l]];
        bb[l] = (const float*)d_in[i_bb[l]];
    }
    const float* scw  = (const float*)d_in[i_scw];
    const float* scb  = (const float*)d_in[i_scb];
    const float* ew   = (const float*)d_in[17];
    const float* fw0  = (const float*)d_in[18];
    const float* fb0  = (const float*)d_in[19];
    const float* fg0  = (const float*)d_in[20];
    const float* fbe0 = (const float*)d_in[21];
    const float* fw1  = (const float*)d_in[22];
    const float* fb1  = (const float*)d_in[23];
    const float* fg1  = (const float*)d_in[24];
    const float* fbe1 = (const float*)d_in[25];
    const float* fw2  = (const float*)d_in[26];
    const float* fb2  = (const float*)d_in[27];
    const float* pw0  = (const float*)d_in[28];
    const float* pb0  = (const float*)d_in[29];
    const float* pw1  = (const float*)d_in[30];
    const float* pb1  = (const float*)d_in[31];

    float *pA, *pb0_, *pb1_, *pb2_, *pb3_, *psm;
    cudaGetSymbolAddress((void**)&pA,   g_A);
    cudaGetSymbolAddress((void**)&pb0_, g_buf0);
    cudaGetSymbolAddress((void**)&pb1_, g_buf1);
    cudaGetSymbolAddress((void**)&pb2_, g_buf2);
    cudaGetSymbolAddress((void**)&pb3_, g_buf3);
    cudaGetSymbolAddress((void**)&psm,  g_small);

    cudaFuncSetAttribute(k_tgemm3, cudaFuncAttributeMaxDynamicSharedMemorySize, SMEM3_BYTES);
    cudaFuncSetAttribute(k_tedge3, cudaFuncAttributeMaxDynamicSharedMemorySize, SMEM3_BYTES);

    float* out_z     = (float*)d_out;                      // 32768*256
    float* out_adj   = out_z + (size_t)NN * HD;            // 256*128*128
    float* out_xrec  = out_adj + (size_t)NB * MAXN * MAXN; // 32768*128
    float* out_zg    = out_xrec + (size_t)NN * FD;         // 256*256
    float* out_zgmlp = out_zg + (size_t)NB * HD;           // 256*256

    // ---- build normalized adjacency (reused by all 3 layers) ----
    k_initdeg<<<NN / 256, 256>>>();
    k_deg<<<NE / 256, 256>>>(dst);
    k_dinv<<<NN / 256, 256>>>();
    k_clearA<<<(NB * MAXN * MAXN) / 256, 256>>>();
    k_buildA<<<NE / 256, 256>>>(src, dst);
    k_diagA<<<NN / 256, 256>>>();

    dim3 gBig(HD / 128, NN / 128);       // 2 x 256
    dim3 gAgg(HD / 128, 1, NB);          // batched aggregation (M=128/graph)
    dim3 gEdge(1, 1, NB);
    dim3 gXrec(FD / 128, NN / 128);      // 1 x 256
    dim3 gSmall(HD / 128, NB / 128);     // 2 x 2
    int nElem = (NN * HD) / 256;
    long sAgg_A = (long)MAXN * MAXN, sAgg_BC = (long)MAXN * HD;

    // ---- GCN layer 0 ----
    k_tgemm3<<<gBig, 256, SMEM3_BYTES>>>(x, gw[0], nullptr, pb1_, HD, FD, 0, 0, 0, 0);
    k_tgemm3<<<gBig, 256, SMEM3_BYTES>>>(x, scw, scb, pb3_, HD, FD, 0, 0, 0, 0);
    k_tgemm3<<<gAgg, 256, SMEM3_BYTES>>>(pA, pb1_, gb[0], pb2_, HD, MAXN, 0, sAgg_A, sAgg_BC, sAgg_BC);
    k_clearsums<<<1, 256>>>();
    k_bnstats<<<NN / 128, 256>>>(pb2_);
    k_bnapply<<<nElem, 256>>>(pb2_, pb3_, bg[0], bb[0], pb0_, 1);

    // ---- GCN layer 1 (residual = input) ----
    k_tgemm3<<<gBig, 256, SMEM3_BYTES>>>(pb0_, gw[1], nullptr, pb1_, HD, HD, 0, 0, 0, 0);
    k_tgemm3<<<gAgg, 256, SMEM3_BYTES>>>(pA, pb1_, gb[1], pb2_, HD, MAXN, 0, sAgg_A, sAgg_BC, sAgg_BC);
    k_clearsums<<<1, 256>>>();
    k_bnstats<<<NN / 128, 256>>>(pb2_);
    k_bnapply<<<nElem, 256>>>(pb2_, pb0_, bg[1], bb[1], pb3_, 1);

    // ---- GCN layer 2 ----
    k_tgemm3<<<gBig, 256, SMEM3_BYTES>>>(pb3_, gw[2], nullptr, pb1_, HD, HD, 0, 0, 0, 0);
    k_tgemm3<<<gAgg, 256, SMEM3_BYTES>>>(pA, pb1_, gb[2], pb2_, HD, MAXN, 0, sAgg_A, sAgg_BC, sAgg_BC);
    k_clearsums<<<1, 256>>>();
    k_bnstats<<<NN / 128, 256>>>(pb2_);
    k_bnapply<<<nElem, 256>>>(pb2_, pb3_, bg[2], bb[2], pb0_, 1);

    // ---- L2 normalize -> z ----
    k_l2<<<NN / 8, 256>>>(pb0_, out_z);

    // ---- bilinear edge decoder ----
    k_tgemm3<<<gBig, 256, SMEM3_BYTES>>>(out_z, ew, nullptr, pb1_, HD, HD, 0, 0, 0, 0);
    k_tedge3<<<gEdge, 256, SMEM3_BYTES>>>(pb1_, out_z, out_adj);

    // ---- feature decoder ----
    k_tgemm3<<<gBig, 256, SMEM3_BYTES>>>(out_z, fw0, fb0, pb2_, HD, HD, 1, 0, 0, 0);
    k_clearsums<<<1, 256>>>();
    k_bnstats<<<NN / 128, 256>>>(pb2_);
    k_bnapply<<<nElem, 256>>>(pb2_, pb2_, fg0, fbe0, pb3_, 0);
    k_tgemm3<<<gBig, 256, SMEM3_BYTES>>>(pb3_, fw1, fb1, pb1_, HD, HD, 1, 0, 0, 0);
    k_clearsums<<<1, 256>>>();
    k_bnstats<<<NN / 128, 256>>>(pb1_);
    k_bnapply<<<nElem, 256>>>(pb1_, pb1_, fg1, fbe1, pb2_, 0);
    k_tgemm3<<<gXrec, 256, SMEM3_BYTES>>>(pb2_, fw2, fb2, out_xrec, FD, HD, 0, 0, 0, 0);

    // ---- pooling + MLP head ----
    k_pool<<<NB, HD>>>(out_z, out_zg);
    k_tgemm3<<<gSmall, 256, SMEM3_BYTES>>>(out_zg, pw0, pb0, psm, HD, HD, 1, 0, 0, 0);
    k_tgemm3<<<gSmall, 256, SMEM3_BYTES>>>(psm, pw1, pb1, out_zgmlp, HD, HD, 0, 0, 0, 0);
}

// round 6
// speedup vs baseline: 1.7818x; 1.3605x over previous
#include <cuda_runtime.h>
#include <cuda_bf16.h>
#include <math.h>

#define NN 32768      // total nodes
#define FD 128        // input feature dim
#define HD 256        // hidden dim
#define NB 256        // graphs
#define MAXN 128      // nodes per graph
#define NE 524288     // edges
#define EPS_BN 1e-5f

// ---------------- scratch (device globals; no allocation allowed) ----------
__device__ float g_deg[NN];
__device__ float g_A[(size_t)NB * MAXN * MAXN];     // normalized adjacency (16 MB)
__device__ float g_buf0[(size_t)NN * HD];
__device__ float g_buf1[(size_t)NN * HD];
__device__ float g_buf2[(size_t)NN * HD];
__device__ float g_buf3[(size_t)NN * HD];
__device__ float g_sum[HD];
__device__ float g_sumsq[HD];
__device__ float g_small[NB * HD];

// ---------------- small utility kernels -----------------------------------
__global__ void k_initdeg() {
    int i = blockIdx.x * blockDim.x + threadIdx.x;
    if (i < NN) g_deg[i] = 1.0f;
}

__global__ void k_deg(const int* __restrict__ dst) {
    int e = blockIdx.x * blockDim.x + threadIdx.x;
    if (e < NE) {
        int g = e >> 11;  // E / B = 2048 edges per graph
        atomicAdd(&g_deg[g * MAXN + dst[e]], 1.0f);
    }
}

__global__ void k_dinv() {
    int i = blockIdx.x * blockDim.x + threadIdx.x;
    if (i < NN) g_deg[i] = rsqrtf(fmaxf(g_deg[i], 1.0f));
}

__global__ void k_clearA() {
    size_t i = (size_t)blockIdx.x * blockDim.x + threadIdx.x;
    if (i < (size_t)NB * MAXN * MAXN) g_A[i] = 0.0f;
}

__global__ void k_buildA(const int* __restrict__ src, const int* __restrict__ dst) {
    int e = blockIdx.x * blockDim.x + threadIdx.x;
    if (e < NE) {
        int g = e >> 11;
        int s = src[e], d = dst[e];
        float nrm = g_deg[g * MAXN + s] * g_deg[g * MAXN + d];
        atomicAdd(&g_A[((size_t)g * MAXN + d) * MAXN + s], nrm);
    }
}

__global__ void k_diagA() {
    int i = blockIdx.x * blockDim.x + threadIdx.x;
    if (i < NN) {
        int g = i / MAXN, l = i % MAXN;
        float di = g_deg[i];
        g_A[((size_t)g * MAXN + l) * MAXN + l] += di * di;
    }
}

__global__ void k_clearsums() {
    int i = threadIdx.x;
    if (i < HD) { g_sum[i] = 0.0f; g_sumsq[i] = 0.0f; }
}

// ---------------- bf16 split-precision tensor-core GEMM --------------------
// C[.,N] = A[.,K] @ B[K,N] (+bias)(+relu), batched via blockIdx.z strides.
// Block tile 128x128x32, 8 warps (2x4), warp tile 64x32, mma.m16n8k16.bf16.
// a = hi + lo (bf16 each); acc += ah*bh + ah*bl + al*bh  (~2^-16 accuracy)

// pack (lo-half = x = k_even, hi-half = y = k_odd) as bf16x2
__device__ __forceinline__ unsigned pack_bf2(float x, float y) {
    unsigned r;
    asm("cvt.rn.bf16x2.f32 %0, %1, %2;" : "=r"(r) : "f"(y), "f"(x));
    return r;
}
// residual after bf16 rounding of both halves
__device__ __forceinline__ unsigned pack_bf2_lo(float x, float y, unsigned h) {
    __nv_bfloat162 hb = *reinterpret_cast<__nv_bfloat162*>(&h);
    float rx = x - __bfloat162float(hb.x);
    float ry = y - __bfloat162float(hb.y);
    unsigned r;
    asm("cvt.rn.bf16x2.f32 %0, %1, %2;" : "=r"(r) : "f"(ry), "f"(rx));
    return r;
}

#define MMA_BF16(d, a0, a1, a2, a3, b0, b1) \
    asm volatile("mma.sync.aligned.m16n8k16.row.col.f32.bf16.bf16.f32 " \
                 "{%0,%1,%2,%3},{%4,%5,%6,%7},{%8,%9},{%0,%1,%2,%3};" \
                 : "+f"(d[0]), "+f"(d[1]), "+f"(d[2]), "+f"(d[3]) \
                 : "r"(a0), "r"(a1), "r"(a2), "r"(a3), "r"(b0), "r"(b1))

#define AST 20    // A kpair stride (16 kpairs padded to 20 -> conflict-free)
#define BST 136   // B n stride (128 padded to 136 -> conflict-free)

__global__ void __launch_bounds__(256) k_bgemm(
    const float* __restrict__ A, const float* __restrict__ B,
    const float* __restrict__ bias, float* __restrict__ C,
    int N, int K, int relu, long sA, long sB, long sC)
{
    __shared__ unsigned Ah[128 * AST], Al[128 * AST];
    __shared__ unsigned Bh[16 * BST],  Bl[16 * BST];

    long g = blockIdx.z;
    A += g * sA; B += g * sB; C += g * sC;

    const int tid = threadIdx.x, lane = tid & 31, wid = tid >> 5;
    const int wm = wid >> 2, wn = wid & 3;      // warp tile (wm*64, wn*32)
    const int gp = lane >> 2, tg = lane & 3;
    const int row0 = blockIdx.y * 128, col0 = blockIdx.x * 128;

    const int la_r = tid >> 3, la_kp = (tid & 7) * 2;   // A: float4 = 2 kpairs
    const int lb_kp = tid >> 5, lb_n = (tid & 31) * 4;  // B: kp + 8j, 4 cols

    const float* Ap = A + (size_t)(row0 + la_r) * K + la_kp * 2;
    const float* Bp = B + (size_t)(lb_kp * 2) * N + col0 + lb_n;

    float4 pa[4], pb0[2], pb1[2];
#pragma unroll
    for (int j = 0; j < 4; j++)
        pa[j] = *(const float4*)(Ap + (size_t)(j * 32) * K);
#pragma unroll
    for (int j = 0; j < 2; j++) {   // kp = lb_kp + 8j : rows 2kp, 2kp+1
        pb0[j] = *(const float4*)(Bp + (size_t)(j * 16) * N);
        pb1[j] = *(const float4*)(Bp + (size_t)(j * 16 + 1) * N);
    }

    float acc[4][4][4] = {};
    const int nk = K >> 5;

    for (int kt = 0; kt < nk; kt++) {
        if (kt) __syncthreads();
#pragma unroll
        for (int j = 0; j < 4; j++) {
            int base = (la_r + j * 32) * AST + la_kp;
            unsigned h0 = pack_bf2(pa[j].x, pa[j].y);
            unsigned h1 = pack_bf2(pa[j].z, pa[j].w);
            Ah[base] = h0; Ah[base + 1] = h1;
            Al[base]     = pack_bf2_lo(pa[j].x, pa[j].y, h0);
            Al[base + 1] = pack_bf2_lo(pa[j].z, pa[j].w, h1);
        }
#pragma unroll
        for (int j = 0; j < 2; j++) {
            int kp = lb_kp + 8 * j;
            int base = kp * BST + lb_n;
#pragma unroll
            for (int c = 0; c < 4; c++) {
                float e = (&pb0[j].x)[c], o = (&pb1[j].x)[c];
                unsigned h = pack_bf2(e, o);
                Bh[base + c] = h;
                Bl[base + c] = pack_bf2_lo(e, o, h);
            }
        }
        __syncthreads();
        if (kt + 1 < nk) {
            Ap += 32;
            Bp += (size_t)32 * N;
#pragma unroll
            for (int j = 0; j < 4; j++)
                pa[j] = *(const float4*)(Ap + (size_t)(j * 32) * K);
#pragma unroll
            for (int j = 0; j < 2; j++) {
                pb0[j] = *(const float4*)(Bp + (size_t)(j * 16) * N);
                pb1[j] = *(const float4*)(Bp + (size_t)(j * 16 + 1) * N);
            }
        }
#pragma unroll
        for (int s = 0; s < 2; s++) {
            const int kp0 = s * 8 + tg;
            unsigned ah[4][4], al[4][4], bh[4][2], bl[4][2];
#pragma unroll
            for (int mi = 0; mi < 4; mi++) {
                int r = wm * 64 + mi * 16 + gp;
                ah[mi][0] = Ah[r * AST + kp0];
                ah[mi][1] = Ah[(r + 8) * AST + kp0];
                ah[mi][2] = Ah[r * AST + kp0 + 4];
                ah[mi][3] = Ah[(r + 8) * AST + kp0 + 4];
                al[mi][0] = Al[r * AST + kp0];
                al[mi][1] = Al[(r + 8) * AST + kp0];
                al[mi][2] = Al[r * AST + kp0 + 4];
                al[mi][3] = Al[(r + 8) * AST + kp0 + 4];
            }
#pragma unroll
            for (int ni = 0; ni < 4; ni++) {
                int c = wn * 32 + ni * 8 + gp;
                bh[ni][0] = Bh[kp0 * BST + c];
                bh[ni][1] = Bh[(kp0 + 4) * BST + c];
                bl[ni][0] = Bl[kp0 * BST + c];
                bl[ni][1] = Bl[(kp0 + 4) * BST + c];
            }
#pragma unroll
            for (int mi = 0; mi < 4; mi++)
#pragma unroll
                for (int ni = 0; ni < 4; ni++) {
                    MMA_BF16(acc[mi][ni], ah[mi][0], ah[mi][1], ah[mi][2], ah[mi][3],
                             bl[ni][0], bl[ni][1]);
                    MMA_BF16(acc[mi][ni], al[mi][0], al[mi][1], al[mi][2], al[mi][3],
                             bh[ni][0], bh[ni][1]);
                    MMA_BF16(acc[mi][ni], ah[mi][0], ah[mi][1], ah[mi][2], ah[mi][3],
                             bh[ni][0], bh[ni][1]);
                }
        }
    }

#pragma unroll
    for (int mi = 0; mi < 4; mi++) {
        int r = row0 + wm * 64 + mi * 16 + gp;
#pragma unroll
        for (int ni = 0; ni < 4; ni++) {
            int c = col0 + wn * 32 + ni * 8 + tg * 2;
            float v0 = acc[mi][ni][0], v1 = acc[mi][ni][1];
            float v2 = acc[mi][ni][2], v3 = acc[mi][ni][3];
            if (bias) {
                float b0 = bias[c], b1 = bias[c + 1];
                v0 += b0; v1 += b1; v2 += b0; v3 += b1;
            }
            if (relu) {
                v0 = fmaxf(v0, 0.0f); v1 = fmaxf(v1, 0.0f);
                v2 = fmaxf(v2, 0.0f); v3 = fmaxf(v3, 0.0f);
            }
            float2 w0 = {v0, v1}, w1 = {v2, v3};
            *(float2*)&C[(size_t)r * N + c] = w0;
            *(float2*)&C[(size_t)(r + 8) * N + c] = w1;
        }
    }
}

// ---------------- edge decoder: adj[g] = sigmoid(ZW[g] @ z[g]^T), diag=0 ---
// per graph: (128 x 256) @ (256 x 128).  One block per graph. bf16 split.
__global__ void __launch_bounds__(256) k_bedge(
    const float* __restrict__ ZW, const float* __restrict__ z,
    float* __restrict__ adj)
{
    __shared__ unsigned Ah[128 * AST], Al[128 * AST];
    __shared__ unsigned Bh[16 * BST],  Bl[16 * BST];

    const int g = blockIdx.z;
    const float* Ab = ZW + (size_t)g * MAXN * HD;
    const float* Bb = z  + (size_t)g * MAXN * HD;

    const int tid = threadIdx.x, lane = tid & 31, wid = tid >> 5;
    const int wm = wid >> 2, wn = wid & 3;
    const int gp = lane >> 2, tg = lane & 3;

    const int la_r = tid >> 3, la_kp = (tid & 7) * 2;
    const int lb_n = tid >> 3, lb_kp = (tid & 7) * 2;   // z row n, 2 kpairs

    float acc[4][4][4] = {};

    for (int kt = 0; kt < HD / 32; kt++) {
        const int k0 = kt * 32;
        if (kt) __syncthreads();
#pragma unroll
        for (int j = 0; j < 4; j++) {
            float4 a = *(const float4*)(Ab + (size_t)(la_r + j * 32) * HD + k0 + la_kp * 2);
            int base = (la_r + j * 32) * AST + la_kp;
            unsigned h0 = pack_bf2(a.x, a.y);
            unsigned h1 = pack_bf2(a.z, a.w);
            Ah[base] = h0; Ah[base + 1] = h1;
            Al[base]     = pack_bf2_lo(a.x, a.y, h0);
            Al[base + 1] = pack_bf2_lo(a.z, a.w, h1);

            int n = lb_n + j * 32;
            float4 b = *(const float4*)(Bb + (size_t)n * HD + k0 + lb_kp * 2);
            unsigned bh0 = pack_bf2(b.x, b.y);
            unsigned bh1 = pack_bf2(b.z, b.w);
            Bh[lb_kp * BST + n] = bh0;
            Bh[(lb_kp + 1) * BST + n] = bh1;
            Bl[lb_kp * BST + n]       = pack_bf2_lo(b.x, b.y, bh0);
            Bl[(lb_kp + 1) * BST + n] = pack_bf2_lo(b.z, b.w, bh1);
        }
        __syncthreads();
#pragma unroll
        for (int s = 0; s < 2; s++) {
            const int kp0 = s * 8 + tg;
            unsigned ah[4][4], al[4][4], bh[4][2], bl[4][2];
#pragma unroll
            for (int mi = 0; mi < 4; mi++) {
                int r = wm * 64 + mi * 16 + gp;
                ah[mi][0] = Ah[r * AST + kp0];
                ah[mi][1] = Ah[(r + 8) * AST + kp0];
                ah[mi][2] = Ah[r * AST + kp0 + 4];
                ah[mi][3] = Ah[(r + 8) * AST + kp0 + 4];
                al[mi][0] = Al[r * AST + kp0];
                al[mi][1] = Al[(r + 8) * AST + kp0];
                al[mi][2] = Al[r * AST + kp0 + 4];
                al[mi][3] = Al[(r + 8) * AST + kp0 + 4];
            }
#pragma unroll
            for (int ni = 0; ni < 4; ni++) {
                int c = wn * 32 + ni * 8 + gp;
                bh[ni][0] = Bh[kp0 * BST + c];
                bh[ni][1] = Bh[(kp0 + 4) * BST + c];
                bl[ni][0] = Bl[kp0 * BST + c];
                bl[ni][1] = Bl[(kp0 + 4) * BST + c];
            }
#pragma unroll
            for (int mi = 0; mi < 4; mi++)
#pragma unroll
                for (int ni = 0; ni < 4; ni++) {
                    MMA_BF16(acc[mi][ni], ah[mi][0], ah[mi][1], ah[mi][2], ah[mi][3],
                             bl[ni][0], bl[ni][1]);
                    MMA_BF16(acc[mi][ni], al[mi][0], al[mi][1], al[mi][2], al[mi][3],
                             bh[ni][0], bh[ni][1]);
                    MMA_BF16(acc[mi][ni], ah[mi][0], ah[mi][1], ah[mi][2], ah[mi][3],
                             bh[ni][0], bh[ni][1]);
                }
        }
    }

    float* out = adj + (size_t)g * MAXN * MAXN;
#pragma unroll
    for (int mi = 0; mi < 4; mi++) {
        int n = wm * 64 + mi * 16 + gp;
#pragma unroll
        for (int ni = 0; ni < 4; ni++) {
            int m = wn * 32 + ni * 8 + tg * 2;
            float v0 = 1.0f / (1.0f + expf(-acc[mi][ni][0]));
            float v1 = 1.0f / (1.0f + expf(-acc[mi][ni][1]));
            float v2 = 1.0f / (1.0f + expf(-acc[mi][ni][2]));
            float v3 = 1.0f / (1.0f + expf(-acc[mi][ni][3]));
            if (n == m) v0 = 0.0f;
            if (n == m + 1) v1 = 0.0f;
            if (n + 8 == m) v2 = 0.0f;
            if (n + 8 == m + 1) v3 = 0.0f;
            float2 w0 = {v0, v1}, w1 = {v2, v3};
            *(float2*)&out[(size_t)n * MAXN + m] = w0;
            *(float2*)&out[(size_t)(n + 8) * MAXN + m] = w1;
        }
    }
}

// ---------------- BN stats: per-column sum & sumsq over NN rows ------------
__global__ void k_bnstats(const float* __restrict__ x) {
    int c = threadIdx.x;
    int r0 = blockIdx.x * 128;
    float s = 0.0f, ss = 0.0f;
    for (int r = 0; r < 128; r++) {
        float v = x[(size_t)(r0 + r) * HD + c];
        s += v; ss += v * v;
    }
    atomicAdd(&g_sum[c], s);
    atomicAdd(&g_sumsq[c], ss);
}

// mode 0: y = bn(x)        mode 1: y = relu(relu(bn(x)) + res)
__global__ void k_bnapply(const float* __restrict__ x, const float* __restrict__ res,
                          const float* __restrict__ gam, const float* __restrict__ bet,
                          float* __restrict__ y, int mode)
{
    size_t i = (size_t)blockIdx.x * blockDim.x + threadIdx.x;
    if (i >= (size_t)NN * HD) return;
    int c = (int)(i & (HD - 1));
    float m = g_sum[c] * (1.0f / NN);
    float v = g_sumsq[c] * (1.0f / NN) - m * m;
    float w = (x[i] - m) * rsqrtf(v + EPS_BN) * gam[c] + bet[c];
    if (mode) {
        w = fmaxf(w, 0.0f) + res[i];
        w = fmaxf(w, 0.0f);
    }
    y[i] = w;
}

// ---------------- row-wise L2 normalize (warp per row) ---------------------
__global__ void k_l2(const float* __restrict__ z, float* __restrict__ out) {
    int row = blockIdx.x * 8 + (threadIdx.x >> 5);
    int lane = threadIdx.x & 31;
    const float* p = z + (size_t)row * HD;
    float s = 0.0f;
    for (int k = lane; k < HD; k += 32) { float v = p[k]; s += v * v; }
#pragma unroll
    for (int o = 16; o; o >>= 1) s += __shfl_xor_sync(0xFFFFFFFFu, s, o);
    float inv = 1.0f / fmaxf(sqrtf(s), 1e-12f);
    for (int k = lane; k < HD; k += 32) out[(size_t)row * HD + k] = p[k] * inv;
}

// ---------------- per-graph max pool ---------------------------------------
__global__ void k_pool(const float* __restrict__ z, float* __restrict__ zg) {
    int g = blockIdx.x;
    int c = threadIdx.x;
    float m = z[((size_t)g * MAXN) * HD + c];
    for (int r = 1; r < MAXN; r++)
        m = fmaxf(m, z[((size_t)g * MAXN + r) * HD + c]);
    zg[(size_t)g * HD + c] = m;
}

// ---------------- host orchestration ---------------------------------------
extern "C" void kernel_launch(void* const* d_in, const int* in_sizes, int n_in,
                              void* d_out, int out_size)
{
    const float* x   = (const float*)d_in[0];
    const int*   src = (const int*)d_in[1];
    const int*   dst = (const int*)d_in[2];

    int i_gw[3], i_gb[3], i_bg[3], i_bb[3], i_scw, i_scb;
    if (in_sizes[7] == 65536) {  // dict order
        for (int l = 0; l < 3; l++) {
            i_gw[l] = 3 + 4 * l; i_gb[l] = 4 + 4 * l;
            i_bg[l] = 5 + 4 * l; i_bb[l] = 6 + 4 * l;
        }
        i_scw = 15; i_scb = 16;
    } else {                      // signature order
        i_gw[0] = 3; i_gb[0] = 4; i_bg[0] = 5; i_bb[0] = 6;
        i_scw = 7; i_scb = 8;
        i_gw[1] = 9;  i_gb[1] = 10; i_bg[1] = 11; i_bb[1] = 12;
        i_gw[2] = 13; i_gb[2] = 14; i_bg[2] = 15; i_bb[2] = 16;
    }
    const float* gw[3]; const float* gb[3]; const float* bg[3]; const float* bb[3];
    for (int l = 0; l < 3; l++) {
        gw[l] = (const float*)d_in[i_gw[l]];
        gb[l] = (const float*)d_in[i_gb[l]];
        bg[l] = (const float*)d_in[i_bg[l]];
        bb[l] = (const float*)d_in[i_bb[l]];
    }
    const float* scw  = (const float*)d_in[i_scw];
    const float* scb  = (const float*)d_in[i_scb];
    const float* ew   = (const float*)d_in[17];
    const float* fw0  = (const float*)d_in[18];
    const float* fb0  = (const float*)d_in[19];
    const float* fg0  = (const float*)d_in[20];
    const float* fbe0 = (const float*)d_in[21];
    const float* fw1  = (const float*)d_in[22];
    const float* fb1  = (const float*)d_in[23];
    const float* fg1  = (const float*)d_in[24];
    const float* fbe1 = (const float*)d_in[25];
    const float* fw2  = (const float*)d_in[26];
    const float* fb2  = (const float*)d_in[27];
    const float* pw0  = (const float*)d_in[28];
    const float* pb0  = (const float*)d_in[29];
    const float* pw1  = (const float*)d_in[30];
    const float* pb1  = (const float*)d_in[31];

    float *pA, *pb0_, *pb1_, *pb2_, *pb3_, *psm;
    cudaGetSymbolAddress((void**)&pA,   g_A);
    cudaGetSymbolAddress((void**)&pb0_, g_buf0);
    cudaGetSymbolAddress((void**)&pb1_, g_buf1);
    cudaGetSymbolAddress((void**)&pb2_, g_buf2);
    cudaGetSymbolAddress((void**)&pb3_, g_buf3);
    cudaGetSymbolAddress((void**)&psm,  g_small);

    float* out_z     = (float*)d_out;                      // 32768*256
    float* out_adj   = out_z + (size_t)NN * HD;            // 256*128*128
    float* out_xrec  = out_adj + (size_t)NB * MAXN * MAXN; // 32768*128
    float* out_zg    = out_xrec + (size_t)NN * FD;         // 256*256
    float* out_zgmlp = out_zg + (size_t)NB * HD;           // 256*256

    // ---- build normalized adjacency (reused by all 3 layers) ----
    k_initdeg<<<NN / 256, 256>>>();
    k_deg<<<NE / 256, 256>>>(dst);
    k_dinv<<<NN / 256, 256>>>();
    k_clearA<<<(NB * MAXN * MAXN) / 256, 256>>>();
    k_buildA<<<NE / 256, 256>>>(src, dst);
    k_diagA<<<NN / 256, 256>>>();

    dim3 gBig(HD / 128, NN / 128);       // 2 x 256
    dim3 gAgg(HD / 128, 1, NB);          // batched aggregation (M=128/graph)
    dim3 gEdge(1, 1, NB);
    dim3 gXrec(FD / 128, NN / 128);      // 1 x 256
    dim3 gSmall(HD / 128, NB / 128);     // 2 x 2
    int nElem = (NN * HD) / 256;
    long sAgg_A = (long)MAXN * MAXN, sAgg_BC = (long)MAXN * HD;

    // ---- GCN layer 0 ----
    k_bgemm<<<gBig, 256>>>(x, gw[0], nullptr, pb1_, HD, FD, 0, 0, 0, 0);
    k_bgemm<<<gBig, 256>>>(x, scw, scb, pb3_, HD, FD, 0, 0, 0, 0);
    k_bgemm<<<gAgg, 256>>>(pA, pb1_, gb[0], pb2_, HD, MAXN, 0, sAgg_A, sAgg_BC, sAgg_BC);
    k_clearsums<<<1, 256>>>();
    k_bnstats<<<NN / 128, 256>>>(pb2_);
    k_bnapply<<<nElem, 256>>>(pb2_, pb3_, bg[0], bb[0], pb0_, 1);

    // ---- GCN layer 1 (residual = input) ----
    k_bgemm<<<gBig, 256>>>(pb0_, gw[1], nullptr, pb1_, HD, HD, 0, 0, 0, 0);
    k_bgemm<<<gAgg, 256>>>(pA, pb1_, gb[1], pb2_, HD, MAXN, 0, sAgg_A, sAgg_BC, sAgg_BC);
    k_clearsums<<<1, 256>>>();
    k_bnstats<<<NN / 128, 256>>>(pb2_);
    k_bnapply<<<nElem, 256>>>(pb2_, pb0_, bg[1], bb[1], pb3_, 1);

    // ---- GCN layer 2 ----
    k_bgemm<<<gBig, 256>>>(pb3_, gw[2], nullptr, pb1_, HD, HD, 0, 0, 0, 0);
    k_bgemm<<<gAgg, 256>>>(pA, pb1_, gb[2], pb2_, HD, MAXN, 0, sAgg_A, sAgg_BC, sAgg_BC);
    k_clearsums<<<1, 256>>>();
    k_bnstats<<<NN / 128, 256>>>(pb2_);
    k_bnapply<<<nElem, 256>>>(pb2_, pb3_, bg[2], bb[2], pb0_, 1);

    // ---- L2 normalize -> z ----
    k_l2<<<NN / 8, 256>>>(pb0_, out_z);

    // ---- bilinear edge decoder ----
    k_bgemm<<<gBig, 256>>>(out_z, ew, nullptr, pb1_, HD, HD, 0, 0, 0, 0);
    k_bedge<<<gEdge, 256>>>(pb1_, out_z, out_adj);

    // ---- feature decoder ----
    k_bgemm<<<gBig, 256>>>(out_z, fw0, fb0, pb2_, HD, HD, 1, 0, 0, 0);
    k_clearsums<<<1, 256>>>();
    k_bnstats<<<NN / 128, 256>>>(pb2_);
    k_bnapply<<<nElem, 256>>>(pb2_, pb2_, fg0, fbe0, pb3_, 0);
    k_bgemm<<<gBig, 256>>>(pb3_, fw1, fb1, pb1_, HD, HD, 1, 0, 0, 0);
    k_clearsums<<<1, 256>>>();
    k_bnstats<<<NN / 128, 256>>>(pb1_);
    k_bnapply<<<nElem, 256>>>(pb1_, pb1_, fg1, fbe1, pb2_, 0);
    k_bgemm<<<gXrec, 256>>>(pb2_, fw2, fb2, out_xrec, FD, HD, 0, 0, 0, 0);

    // ---- pooling + MLP head ----
    k_pool<<<NB, HD>>>(out_z, out_zg);
    k_bgemm<<<gSmall, 256>>>(out_zg, pw0, pb0, psm, HD, HD, 1, 0, 0, 0);
    k_bgemm<<<gSmall, 256>>>(psm, pw1, pb1, out_zgmlp, HD, HD, 0, 0, 0, 0);
}